// round 16
// baseline (speedup 1.0000x reference)
#include <cuda_runtime.h>
#include <cuda_bf16.h>
#include <mma.h>

using namespace nvcuda;

#define B_NUM 4
#define CNUM  256
#define HWN   4096
#define NH    4
#define HD    64
#define LOG2E 1.4426950408889634f
#define QSCALE (0.125f * LOG2E)
// Schraudolph bf16 exp2 magic: round-to-int bias (2^23+2^22) + 127*128 - 7 (minimax corr)
#define MAGICF 12599161.0f

// ---------------- scratch (device globals; allocation-free rule) ----------
__device__ float g_part [512];
__device__ __nv_bfloat16 g_h [B_NUM * CNUM * HWN];        // GN(x) in bf16, [b][c][pix]
__device__ __nv_bfloat16 g_wqkvb[3 * CNUM * CNUM];        // bf16 weights
__device__ __nv_bfloat16 g_wprojb[CNUM * CNUM];
__device__ __nv_bfloat16 g_qb[B_NUM * NH * HWN * HD];
__device__ __nv_bfloat16 g_kb[B_NUM * NH * HWN * HD];
__device__ __nv_bfloat16 g_vb[B_NUM * NH * HWN * HD];
__device__ __nv_bfloat16 g_ao[B_NUM * HWN * CNUM];        // attention out, bf16

// ---------------- small asm helpers ----------------------------------------
__device__ __forceinline__ unsigned s2u(const void* p) {
    unsigned a;
    asm("{ .reg .u64 t; cvta.to.shared.u64 t, %1; cvt.u32.u64 %0, t; }" : "=r"(a) : "l"(p));
    return a;
}
__device__ __forceinline__ void cpa16(unsigned d, const void* s) {
    asm volatile("cp.async.cg.shared.global [%0], [%1], 16;" :: "r"(d), "l"(s));
}
__device__ __forceinline__ void ldsm4(unsigned* r, unsigned a) {
    asm volatile("ldmatrix.sync.aligned.m8n8.x4.shared.b16 {%0,%1,%2,%3}, [%4];"
        : "=r"(r[0]), "=r"(r[1]), "=r"(r[2]), "=r"(r[3]) : "r"(a));
}
__device__ __forceinline__ void ldsm4t(unsigned* r, unsigned a) {
    asm volatile("ldmatrix.sync.aligned.m8n8.x4.trans.shared.b16 {%0,%1,%2,%3}, [%4];"
        : "=r"(r[0]), "=r"(r[1]), "=r"(r[2]), "=r"(r[3]) : "r"(a));
}
__device__ __forceinline__ void mma_bf(float* c, const unsigned* a, unsigned b0, unsigned b1) {
    asm volatile("mma.sync.aligned.m16n8k16.row.col.f32.bf16.bf16.f32 "
        "{%0,%1,%2,%3}, {%4,%5,%6,%7}, {%8,%9}, {%0,%1,%2,%3};"
        : "+f"(c[0]), "+f"(c[1]), "+f"(c[2]), "+f"(c[3])
        : "r"(a[0]), "r"(a[1]), "r"(a[2]), "r"(a[3]), "r"(b0), "r"(b1));
}
// Schraudolph: t = fma(s,128,MAGIC); low 16 bits of t are bf16(2^s)
__device__ __forceinline__ float ex2t(float s) { return fmaf(s, 128.0f, MAGICF); }
__device__ __forceinline__ float bfval(float t) {
    return __int_as_float(__float_as_int(t) << 16);
}
__device__ __forceinline__ unsigned bfpack(float t0, float t1) {
    return __byte_perm(__float_as_int(t0), __float_as_int(t1), 0x5410);
}
__device__ __forceinline__ unsigned cvtbf2(float lo, float hi) {
    unsigned r; asm("cvt.rn.bf16x2.f32 %0, %1, %2;" : "=r"(r) : "f"(hi), "f"(lo)); return r;
}

// ---------------- kernel 1: GN partial sums + weight conversion ------------
__global__ void gn_partial(const float* __restrict__ x,
                           const float* __restrict__ wqkv,
                           const float* __restrict__ wproj) {
    int blk = blockIdx.x;
    if (blk < 256) {
        const float4* base = (const float4*)x + (size_t)blk * 4096;
        float s = 0.f, s2 = 0.f;
        for (int i = threadIdx.x; i < 4096; i += 256) {
            float4 v = base[i];
            s  += (v.x + v.y) + (v.z + v.w);
            s2 += (v.x*v.x + v.y*v.y) + (v.z*v.z + v.w*v.w);
        }
        __shared__ float r1[256], r2[256];
        r1[threadIdx.x] = s; r2[threadIdx.x] = s2;
        __syncthreads();
        for (int off = 128; off > 0; off >>= 1) {
            if (threadIdx.x < off) {
                r1[threadIdx.x] += r1[threadIdx.x + off];
                r2[threadIdx.x] += r2[threadIdx.x + off];
            }
            __syncthreads();
        }
        if (threadIdx.x == 0) { g_part[blk*2] = r1[0]; g_part[blk*2+1] = r2[0]; }
    } else {
        int wb = blk - 256;                       // 0..63, 4096 floats each
        #pragma unroll
        for (int j = 0; j < 4; j++) {
            int idx = wb * 4096 + j * 1024 + threadIdx.x * 4;
            if (idx < 196608) {
                float4 v = *(const float4*)(wqkv + idx);
                uint2 o;
                o.x = cvtbf2(v.x, v.y); o.y = cvtbf2(v.z, v.w);
                *(uint2*)(g_wqkvb + idx) = o;
            } else {
                int p = idx - 196608;
                float4 v = *(const float4*)(wproj + p);
                uint2 o;
                o.x = cvtbf2(v.x, v.y); o.y = cvtbf2(v.z, v.w);
                *(uint2*)(g_wprojb + p) = o;
            }
        }
    }
}

// ---------------- kernel 2: GN apply (inline final stats) ------------------
__global__ void gn_apply(const float* __restrict__ x,
                         const float* __restrict__ gamma,
                         const float* __restrict__ beta) {
    int bc = blockIdx.x;                          // 1024 blocks (b*256 + c)
    int b = bc >> 8, c = bc & 255;
    int bg = b * 8 + (c >> 5);
    __shared__ float sc_s, bi_s;
    if (threadIdx.x == 0) {
        float s = 0.f, s2 = 0.f;
        #pragma unroll
        for (int i = 0; i < 8; i++) { s += g_part[(bg*8+i)*2]; s2 += g_part[(bg*8+i)*2+1]; }
        float mean = s * (1.f/131072.f);
        float var  = s2 * (1.f/131072.f) - mean*mean;
        float rstd = rsqrtf(var + 1e-5f);
        float sc = rstd * gamma[c];
        sc_s = sc;
        bi_s = beta[c] - mean * sc;
    }
    __syncthreads();
    float sc = sc_s, bi = bi_s;
    const float4* src = (const float4*)(x + (size_t)bc * 4096);
    uint2* dst = (uint2*)(g_h + (size_t)bc * 4096);
    for (int i = threadIdx.x; i < 1024; i += 256) {
        float4 v = src[i];
        uint2 o;
        o.x = cvtbf2(fmaf(v.x, sc, bi), fmaf(v.y, sc, bi));
        o.y = cvtbf2(fmaf(v.z, sc, bi), fmaf(v.w, sc, bi));
        dst[i] = o;
    }
}

// ---------------- kernel 3: QKV GEMM (128x128 tiles, C aliased, 2-pass) ----
#define QKV_AS_ST 136
#define QKV_BOFF  17408
#define QKV_SMEM  35840

__global__ __launch_bounds__(256) void qkv_kernel(const float* __restrict__ bqkv) {
    extern __shared__ char qsm[];
    __nv_bfloat16* As = (__nv_bfloat16*)qsm;                 // [64k][136m]
    __nv_bfloat16* Bs = (__nv_bfloat16*)(qsm + QKV_BOFF);    // [128n][72k]
    float*         Cs = (float*)qsm;                         // [128m][68] (alias)
    int nt = blockIdx.x;     // 0..5
    int mt = blockIdx.y;     // 0..127
    int p0 = mt * 128;
    int b  = p0 >> 12;
    int hw0 = p0 & (HWN - 1);
    int o0 = nt * 128;
    int t = threadIdx.x, w = t >> 5, wm = w & 3, wn = w >> 2;

    wmma::fragment<wmma::accumulator, 16, 16, 16, float> acc[2][4];
    #pragma unroll
    for (int i = 0; i < 2; i++)
        #pragma unroll
        for (int j = 0; j < 4; j++) wmma::fill_fragment(acc[i][j], 0.0f);

    for (int kt = 0; kt < 4; kt++) {
        int c0 = kt * 64;
        __syncthreads();
        #pragma unroll
        for (int i = 0; i < 4; i++) {
            int e = i * 256 + t;
            int m8 = e & 15, k = e >> 4;
            *(uint4*)(As + k * QKV_AS_ST + m8 * 8) =
                *(const uint4*)(g_h + (((size_t)(b * CNUM + c0 + k)) << 12) + hw0 + m8 * 8);
        }
        #pragma unroll
        for (int i = 0; i < 4; i++) {
            int e = i * 256 + t;
            int k8 = e & 7, n = e >> 3;
            *(uint4*)(Bs + n * 72 + k8 * 8) =
                *(const uint4*)(g_wqkvb + (size_t)(o0 + n) * CNUM + c0 + k8 * 8);
        }
        __syncthreads();
        #pragma unroll
        for (int kk = 0; kk < 64; kk += 16) {
            wmma::fragment<wmma::matrix_a, 16, 16, 16, __nv_bfloat16, wmma::col_major> a[2];
            wmma::fragment<wmma::matrix_b, 16, 16, 16, __nv_bfloat16, wmma::col_major> bb[4];
            #pragma unroll
            for (int i = 0; i < 2; i++)
                wmma::load_matrix_sync(a[i], As + kk * QKV_AS_ST + (wm * 32 + i * 16), QKV_AS_ST);
            #pragma unroll
            for (int j = 0; j < 4; j++)
                wmma::load_matrix_sync(bb[j], Bs + (wn * 64 + j * 16) * 72 + kk, 72);
            #pragma unroll
            for (int i = 0; i < 2; i++)
                #pragma unroll
                for (int j = 0; j < 4; j++)
                    wmma::mma_sync(acc[i][j], a[i], bb[j], acc[i][j]);
        }
    }
    #pragma unroll
    for (int p = 0; p < 2; p++) {
        __syncthreads();
        if (wn == p) {
            #pragma unroll
            for (int i = 0; i < 2; i++)
                #pragma unroll
                for (int j = 0; j < 4; j++)
                    wmma::store_matrix_sync(Cs + (wm * 32 + i * 16) * 68 + j * 16,
                                            acc[i][j], 68, wmma::mem_row_major);
        }
        __syncthreads();
        int o0p = o0 + p * 64;
        int which = o0p >> 8;
        int head  = (o0p >> 6) & 3;
        __nv_bfloat16* dst = (which == 0) ? g_qb : (which == 1) ? g_kb : g_vb;
        float mul = (which == 0) ? QSCALE : 1.0f;
        #pragma unroll
        for (int i = 0; i < 16; i++) {
            int e = i * 256 + t;
            int n2 = e & 31, m = e >> 5;
            float v0 = (Cs[m * 68 + n2*2]     + bqkv[o0p + n2*2])     * mul;
            float v1 = (Cs[m * 68 + n2*2 + 1] + bqkv[o0p + n2*2 + 1]) * mul;
            *(unsigned*)(dst + (((size_t)((b * NH + head) * HWN + hw0 + m)) << 6) + n2*2) =
                cvtbf2(v0, v1);
        }
    }
}

// ---------------- kernel 4: attention (128-key iters, per-group dataflow) --
// grid (32, 16). 128 threads, 4 warps x 32 q-rows, 2 CTAs/SM.
// smem: Q[128][72] | K: 2 x [128][72] | V: 2 x [128][72]   (92160 B)
#define ATT_SP 72
#define ATT_KOFF (128 * ATT_SP * 2)                 // 18432
#define ATT_VOFF (ATT_KOFF + 2 * 128 * ATT_SP * 2)  // 55296
#define ATT_SMEM (ATT_VOFF + 2 * 128 * ATT_SP * 2)  // 92160

__global__ __launch_bounds__(128, 2) void attn_kernel() {
    extern __shared__ __align__(16) char dsm[];
    const int SP = ATT_SP;
    int t = threadIdx.x;
    int w = t >> 5, l = t & 31;
    int qb = blockIdx.x, bh = blockIdx.y;
    int q0 = qb * 128;
    const __nv_bfloat16* qp = g_qb + (size_t)bh * HWN * HD + (size_t)q0 * HD;
    const __nv_bfloat16* kp = g_kb + (size_t)bh * HWN * HD;
    const __nv_bfloat16* vp = g_vb + (size_t)bh * HWN * HD;

    unsigned su = s2u(dsm);
    unsigned Qs = su;

    // prefetch K/V block 0 (128 rows each)
    {
        #pragma unroll
        for (int i = 0; i < 8; i++) {
            int c = i * 128 + t;
            int row = c >> 3, col8 = c & 7;
            unsigned so = (unsigned)(row * SP + col8 * 8) * 2;
            cpa16(su + ATT_KOFF + so, kp + (size_t)row * 64 + col8 * 8);
            cpa16(su + ATT_VOFF + so, vp + (size_t)row * 64 + col8 * 8);
        }
        asm volatile("cp.async.commit_group;" ::: "memory");
    }
    // Q tile -> smem
    #pragma unroll
    for (int i = 0; i < 8; i++) {
        int c = i * 128 + t;
        int row = c >> 3, col8 = c & 7;
        *(uint4*)(dsm + (size_t)(row * SP + col8 * 8) * 2) =
            *(const uint4*)(qp + (size_t)row * 64 + col8 * 8);
    }
    __syncthreads();

    int lrow_a = l & 15,  lcol_a = (l >> 4) * 8;
    int lrow_k = (l & 7) + ((l >> 4) << 3), lcol_k = ((l >> 3) & 1) * 8;
    int r0 = w * 32;

    unsigned qf[2][4][4];
    #pragma unroll
    for (int mb = 0; mb < 2; mb++)
        #pragma unroll
        for (int kc = 0; kc < 4; kc++)
            ldsm4(qf[mb][kc],
                  Qs + (unsigned)(((r0 + mb*16 + lrow_a) * SP + kc*16 + lcol_a) * 2));

    float oacc[2][8][4];
    #pragma unroll
    for (int mb = 0; mb < 2; mb++)
        #pragma unroll
        for (int j = 0; j < 8; j++)
            #pragma unroll
            for (int i = 0; i < 4; i++) oacc[mb][j][i] = 0.f;
    float rs[4] = {0.f, 0.f, 0.f, 0.f};

    for (int kb = 0; kb < 32; kb++) {
        asm volatile("cp.async.wait_group 0;" ::: "memory");
        __syncthreads();
        if (kb + 1 < 32) {
            int k0 = (kb + 1) * 128;
            unsigned kd = su + ATT_KOFF + (unsigned)((kb + 1) & 1) * (128 * SP * 2);
            unsigned vd = su + ATT_VOFF + (unsigned)((kb + 1) & 1) * (128 * SP * 2);
            #pragma unroll
            for (int i = 0; i < 8; i++) {
                int c = i * 128 + t;
                int row = c >> 3, col8 = c & 7;
                unsigned so = (unsigned)(row * SP + col8 * 8) * 2;
                cpa16(kd + so, kp + (size_t)(k0 + row) * 64 + col8 * 8);
                cpa16(vd + so, vp + (size_t)(k0 + row) * 64 + col8 * 8);
            }
            asm volatile("cp.async.commit_group;" ::: "memory");
        }
        unsigned kS = su + ATT_KOFF + (unsigned)(kb & 1) * (128 * SP * 2);
        unsigned vS = su + ATT_VOFF + (unsigned)(kb & 1) * (128 * SP * 2);

        // per-group: S(g) -> exp(g) -> PV(g), g over 8 key-groups of 16
        #pragma unroll
        for (int g = 0; g < 8; g++) {
            float s[2][2][4];
            #pragma unroll
            for (int mb = 0; mb < 2; mb++)
                #pragma unroll
                for (int h = 0; h < 2; h++)
                    #pragma unroll
                    for (int i = 0; i < 4; i++) s[mb][h][i] = 0.f;
            #pragma unroll
            for (int kc = 0; kc < 4; kc++) {
                unsigned bb[4];
                ldsm4(bb, kS + (unsigned)(((g*16 + lrow_k) * SP + kc*16 + lcol_k) * 2));
                mma_bf(s[0][0], qf[0][kc], bb[0], bb[1]);
                mma_bf(s[0][1], qf[0][kc], bb[2], bb[3]);
                mma_bf(s[1][0], qf[1][kc], bb[0], bb[1]);
                mma_bf(s[1][1], qf[1][kc], bb[2], bb[3]);
            }
            unsigned pf[2][4];
            #pragma unroll
            for (int mb = 0; mb < 2; mb++) {
                float e0 = ex2t(s[mb][0][0]), e1 = ex2t(s[mb][0][1]);
                float e2 = ex2t(s[mb][0][2]), e3 = ex2t(s[mb][0][3]);
                float f0 = ex2t(s[mb][1][0]), f1 = ex2t(s[mb][1][1]);
                float f2 = ex2t(s[mb][1][2]), f3 = ex2t(s[mb][1][3]);
                pf[mb][0] = bfpack(e0, e1);
                pf[mb][1] = bfpack(e2, e3);
                pf[mb][2] = bfpack(f0, f1);
                pf[mb][3] = bfpack(f2, f3);
                rs[mb*2+0] += (bfval(e0) + bfval(e1)) + (bfval(f0) + bfval(f1));
                rs[mb*2+1] += (bfval(e2) + bfval(e3)) + (bfval(f2) + bfval(f3));
            }
            #pragma unroll
            for (int dg = 0; dg < 4; dg++) {
                unsigned vv[4];
                ldsm4t(vv, vS + (unsigned)(((g*16 + lrow_a) * SP + dg*16 + lcol_a) * 2));
                mma_bf(oacc[0][2*dg],   pf[0], vv[0], vv[1]);
                mma_bf(oacc[0][2*dg+1], pf[0], vv[2], vv[3]);
                mma_bf(oacc[1][2*dg],   pf[1], vv[0], vv[1]);
                mma_bf(oacc[1][2*dg+1], pf[1], vv[2], vv[3]);
            }
        }
    }

    #pragma unroll
    for (int i = 0; i < 4; i++) {
        rs[i] += __shfl_xor_sync(0xffffffffu, rs[i], 1);
        rs[i] += __shfl_xor_sync(0xffffffffu, rs[i], 2);
    }
    int b = bh >> 2, h = bh & 3;
    __nv_bfloat16* aop = g_ao + ((size_t)b * HWN + q0) * CNUM + h * HD;
    #pragma unroll
    for (int mb = 0; mb < 2; mb++) {
        float i0 = 1.0f / rs[mb*2], i1 = 1.0f / rs[mb*2+1];
        int row0 = r0 + mb*16 + (l >> 2);
        int cbase = (l & 3) * 2;
        #pragma unroll
        for (int j = 0; j < 8; j++) {
            *(unsigned*)(aop + (size_t)row0 * CNUM + j*8 + cbase) =
                cvtbf2(oacc[mb][j][0] * i0, oacc[mb][j][1] * i0);
            *(unsigned*)(aop + (size_t)(row0 + 8) * CNUM + j*8 + cbase) =
                cvtbf2(oacc[mb][j][2] * i1, oacc[mb][j][3] * i1);
        }
    }
}

// ---------------- kernel 5: proj GEMM + residual (128x128, aliased C) ------
#define PROJ_BOFF 18432
#define PROJ_SMEM 36864

__global__ __launch_bounds__(256) void proj_kernel(const float* __restrict__ x,
                                                   const float* __restrict__ bproj,
                                                   float* __restrict__ out) {
    extern __shared__ char psm[];
    __nv_bfloat16* As = (__nv_bfloat16*)psm;                  // [128m][72k]
    __nv_bfloat16* Bs = (__nv_bfloat16*)(psm + PROJ_BOFF);    // [128n][72k]
    float*         Cs = (float*)psm;                          // [128m][68] (alias)
    int nt = blockIdx.x;     // 0..1
    int mt = blockIdx.y;     // 0..127
    int p0 = mt * 128;
    int b  = p0 >> 12;
    int hw0 = p0 & (HWN - 1);
    int o0 = nt * 128;
    int t = threadIdx.x, w = t >> 5, wm = w & 3, wn = w >> 2;

    wmma::fragment<wmma::accumulator, 16, 16, 16, float> acc[2][4];
    #pragma unroll
    for (int i = 0; i < 2; i++)
        #pragma unroll
        for (int j = 0; j < 4; j++) wmma::fill_fragment(acc[i][j], 0.0f);

    for (int kt = 0; kt < 4; kt++) {
        int c0 = kt * 64;
        __syncthreads();
        #pragma unroll
        for (int i = 0; i < 4; i++) {
            int e = i * 256 + t;
            int k8 = e & 7, m = e >> 3;
            *(uint4*)(As + m * 72 + k8 * 8) =
                *(const uint4*)(g_ao + ((size_t)(p0 + m)) * CNUM + c0 + k8 * 8);
        }
        #pragma unroll
        for (int i = 0; i < 4; i++) {
            int e = i * 256 + t;
            int k8 = e & 7, n = e >> 3;
            *(uint4*)(Bs + n * 72 + k8 * 8) =
                *(const uint4*)(g_wprojb + (size_t)(o0 + n) * CNUM + c0 + k8 * 8);
        }
        __syncthreads();
        #pragma unroll
        for (int kk = 0; kk < 64; kk += 16) {
            wmma::fragment<wmma::matrix_a, 16, 16, 16, __nv_bfloat16, wmma::row_major> a[2];
            wmma::fragment<wmma::matrix_b, 16, 16, 16, __nv_bfloat16, wmma::col_major> bb[4];
            #pragma unroll
            for (int i = 0; i < 2; i++)
                wmma::load_matrix_sync(a[i], As + (wm * 32 + i * 16) * 72 + kk, 72);
            #pragma unroll
            for (int j = 0; j < 4; j++)
                wmma::load_matrix_sync(bb[j], Bs + (wn * 64 + j * 16) * 72 + kk, 72);
            #pragma unroll
            for (int i = 0; i < 2; i++)
                #pragma unroll
                for (int j = 0; j < 4; j++)
                    wmma::mma_sync(acc[i][j], a[i], bb[j], acc[i][j]);
        }
    }
    #pragma unroll
    for (int p = 0; p < 2; p++) {
        __syncthreads();
        if (wn == p) {
            #pragma unroll
            for (int i = 0; i < 2; i++)
                #pragma unroll
                for (int j = 0; j < 4; j++)
                    wmma::store_matrix_sync(Cs + (wm * 32 + i * 16) * 68 + j * 16,
                                            acc[i][j], 68, wmma::mem_row_major);
        }
        __syncthreads();
        int o0p = o0 + p * 64;
        #pragma unroll
        for (int i = 0; i < 32; i++) {
            int e = i * 256 + t;
            int m = e & 127, n = e >> 7;
            size_t oidx = (((size_t)(b * CNUM + o0p + n)) << 12) + hw0 + m;
            out[oidx] = x[oidx] + Cs[m * 68 + n] + bproj[o0p + n];
        }
    }
}

// ---------------- launch ----------------------------------------------------
extern "C" void kernel_launch(void* const* d_in, const int* in_sizes, int n_in,
                              void* d_out, int out_size) {
    const float* x      = (const float*)d_in[0];
    const float* gamma  = (const float*)d_in[1];
    const float* beta   = (const float*)d_in[2];
    const float* w_qkv  = (const float*)d_in[3];
    const float* b_qkv  = (const float*)d_in[4];
    const float* w_proj = (const float*)d_in[5];
    const float* b_proj = (const float*)d_in[6];
    float* out = (float*)d_out;

    gn_partial<<<320, 256>>>(x, w_qkv, w_proj);
    gn_apply<<<1024, 256>>>(x, gamma, beta);

    cudaFuncSetAttribute(qkv_kernel, cudaFuncAttributeMaxDynamicSharedMemorySize, QKV_SMEM);
    qkv_kernel<<<dim3(6, 128), 256, QKV_SMEM>>>(b_qkv);

    cudaFuncSetAttribute(attn_kernel, cudaFuncAttributeMaxDynamicSharedMemorySize, ATT_SMEM);
    attn_kernel<<<dim3(32, 16), 128, ATT_SMEM>>>();

    cudaFuncSetAttribute(proj_kernel, cudaFuncAttributeMaxDynamicSharedMemorySize, PROJ_SMEM);
    proj_kernel<<<dim3(2, 128), 256, PROJ_SMEM>>>(x, b_proj, out);
}

// round 17
// speedup vs baseline: 1.0606x; 1.0606x over previous
#include <cuda_runtime.h>
#include <cuda_bf16.h>
#include <mma.h>

using namespace nvcuda;

#define B_NUM 4
#define CNUM  256
#define HWN   4096
#define NH    4
#define HD    64
#define LOG2E 1.4426950408889634f
#define QSCALE (0.125f * LOG2E)
// Schraudolph bf16 exp2 magic: round-to-int bias (2^23+2^22) + 127*128 - 7 (minimax corr)
#define MAGICF 12599161.0f

// ---------------- scratch (device globals; allocation-free rule) ----------
__device__ float g_part [512];
__device__ __nv_bfloat16 g_h [B_NUM * CNUM * HWN];        // GN(x) in bf16, [b][c][pix]
__device__ __nv_bfloat16 g_wqkvb[3 * CNUM * CNUM];        // bf16 weights
__device__ __nv_bfloat16 g_wprojb[CNUM * CNUM];
__device__ __nv_bfloat16 g_qb[B_NUM * NH * HWN * HD];
__device__ __nv_bfloat16 g_kb[B_NUM * NH * HWN * HD];
__device__ __nv_bfloat16 g_vb[B_NUM * NH * HWN * HD];
__device__ __nv_bfloat16 g_ao[B_NUM * HWN * CNUM];        // attention out, bf16

// ---------------- small asm helpers ----------------------------------------
__device__ __forceinline__ unsigned s2u(const void* p) {
    unsigned a;
    asm("{ .reg .u64 t; cvta.to.shared.u64 t, %1; cvt.u32.u64 %0, t; }" : "=r"(a) : "l"(p));
    return a;
}
__device__ __forceinline__ void cpa16(unsigned d, const void* s) {
    asm volatile("cp.async.cg.shared.global [%0], [%1], 16;" :: "r"(d), "l"(s));
}
__device__ __forceinline__ void ldsm4(unsigned* r, unsigned a) {
    asm volatile("ldmatrix.sync.aligned.m8n8.x4.shared.b16 {%0,%1,%2,%3}, [%4];"
        : "=r"(r[0]), "=r"(r[1]), "=r"(r[2]), "=r"(r[3]) : "r"(a));
}
__device__ __forceinline__ void ldsm4t(unsigned* r, unsigned a) {
    asm volatile("ldmatrix.sync.aligned.m8n8.x4.trans.shared.b16 {%0,%1,%2,%3}, [%4];"
        : "=r"(r[0]), "=r"(r[1]), "=r"(r[2]), "=r"(r[3]) : "r"(a));
}
__device__ __forceinline__ void mma_bf(float* c, const unsigned* a, unsigned b0, unsigned b1) {
    asm volatile("mma.sync.aligned.m16n8k16.row.col.f32.bf16.bf16.f32 "
        "{%0,%1,%2,%3}, {%4,%5,%6,%7}, {%8,%9}, {%0,%1,%2,%3};"
        : "+f"(c[0]), "+f"(c[1]), "+f"(c[2]), "+f"(c[3])
        : "r"(a[0]), "r"(a[1]), "r"(a[2]), "r"(a[3]), "r"(b0), "r"(b1));
}
// Schraudolph: t = fma(s,128,MAGIC); low 16 bits of t are bf16(2^s)
__device__ __forceinline__ float ex2t(float s) { return fmaf(s, 128.0f, MAGICF); }
__device__ __forceinline__ float bfval(float t) {
    return __int_as_float(__float_as_int(t) << 16);
}
__device__ __forceinline__ unsigned bfpack(float t0, float t1) {
    return __byte_perm(__float_as_int(t0), __float_as_int(t1), 0x5410);
}
__device__ __forceinline__ unsigned cvtbf2(float lo, float hi) {
    unsigned r; asm("cvt.rn.bf16x2.f32 %0, %1, %2;" : "=r"(r) : "f"(hi), "f"(lo)); return r;
}

// ---------------- kernel 1: GN partial sums + weight conversion ------------
__global__ void gn_partial(const float* __restrict__ x,
                           const float* __restrict__ wqkv,
                           const float* __restrict__ wproj) {
    int blk = blockIdx.x;
    if (blk < 256) {
        const float4* base = (const float4*)x + (size_t)blk * 4096;
        float s = 0.f, s2 = 0.f;
        for (int i = threadIdx.x; i < 4096; i += 256) {
            float4 v = base[i];
            s  += (v.x + v.y) + (v.z + v.w);
            s2 += (v.x*v.x + v.y*v.y) + (v.z*v.z + v.w*v.w);
        }
        __shared__ float r1[256], r2[256];
        r1[threadIdx.x] = s; r2[threadIdx.x] = s2;
        __syncthreads();
        for (int off = 128; off > 0; off >>= 1) {
            if (threadIdx.x < off) {
                r1[threadIdx.x] += r1[threadIdx.x + off];
                r2[threadIdx.x] += r2[threadIdx.x + off];
            }
            __syncthreads();
        }
        if (threadIdx.x == 0) { g_part[blk*2] = r1[0]; g_part[blk*2+1] = r2[0]; }
    } else {
        int wb = blk - 256;                       // 0..63, 4096 floats each
        #pragma unroll
        for (int j = 0; j < 4; j++) {
            int idx = wb * 4096 + j * 1024 + threadIdx.x * 4;
            if (idx < 196608) {
                float4 v = *(const float4*)(wqkv + idx);
                uint2 o;
                o.x = cvtbf2(v.x, v.y); o.y = cvtbf2(v.z, v.w);
                *(uint2*)(g_wqkvb + idx) = o;
            } else {
                int p = idx - 196608;
                float4 v = *(const float4*)(wproj + p);
                uint2 o;
                o.x = cvtbf2(v.x, v.y); o.y = cvtbf2(v.z, v.w);
                *(uint2*)(g_wprojb + p) = o;
            }
        }
    }
}

// ---------------- kernel 2: GN apply (inline final stats) ------------------
__global__ void gn_apply(const float* __restrict__ x,
                         const float* __restrict__ gamma,
                         const float* __restrict__ beta) {
    int bc = blockIdx.x;                          // 1024 blocks (b*256 + c)
    int b = bc >> 8, c = bc & 255;
    int bg = b * 8 + (c >> 5);
    __shared__ float sc_s, bi_s;
    if (threadIdx.x == 0) {
        float s = 0.f, s2 = 0.f;
        #pragma unroll
        for (int i = 0; i < 8; i++) { s += g_part[(bg*8+i)*2]; s2 += g_part[(bg*8+i)*2+1]; }
        float mean = s * (1.f/131072.f);
        float var  = s2 * (1.f/131072.f) - mean*mean;
        float rstd = rsqrtf(var + 1e-5f);
        float sc = rstd * gamma[c];
        sc_s = sc;
        bi_s = beta[c] - mean * sc;
    }
    __syncthreads();
    float sc = sc_s, bi = bi_s;
    const float4* src = (const float4*)(x + (size_t)bc * 4096);
    uint2* dst = (uint2*)(g_h + (size_t)bc * 4096);
    for (int i = threadIdx.x; i < 1024; i += 256) {
        float4 v = src[i];
        uint2 o;
        o.x = cvtbf2(fmaf(v.x, sc, bi), fmaf(v.y, sc, bi));
        o.y = cvtbf2(fmaf(v.z, sc, bi), fmaf(v.w, sc, bi));
        dst[i] = o;
    }
}

// ---------------- kernel 3: QKV GEMM (128x128, double-buffered cp.async) ---
// smem: A0 A1 (64x136 bf16, 17408 each) | B0 B1 (128x72 bf16, 18432 each)
// C (128x68 f32, 34816) aliases A0+A1 exactly.
#define QKV_AS_ST 136
#define QKV_AB    17408
#define QKV_BB    18432
#define QKV_BOFF  (2*QKV_AB)
#define QKV_SMEM  (2*QKV_AB + 2*QKV_BB)   // 71680

__global__ __launch_bounds__(256) void qkv_kernel(const float* __restrict__ bqkv) {
    extern __shared__ char qsm[];
    float* Cs = (float*)qsm;                                 // aliases A0+A1
    int nt = blockIdx.x;     // 0..5
    int mt = blockIdx.y;     // 0..127
    int p0 = mt * 128;
    int b  = p0 >> 12;
    int hw0 = p0 & (HWN - 1);
    int o0 = nt * 128;
    int t = threadIdx.x, w = t >> 5, wm = w & 3, wn = w >> 2;
    unsigned su = s2u(qsm);

    auto loadTile = [&](int kt) {
        int c0 = kt * 64;
        unsigned Au = su + (unsigned)(kt & 1) * QKV_AB;
        unsigned Bu = su + QKV_BOFF + (unsigned)(kt & 1) * QKV_BB;
        #pragma unroll
        for (int i = 0; i < 4; i++) {            // A: 64k x 128m
            int e = i * 256 + t;
            int m8 = e & 15, k = e >> 4;
            cpa16(Au + (unsigned)(k * QKV_AS_ST + m8 * 8) * 2,
                  g_h + (((size_t)(b * CNUM + c0 + k)) << 12) + hw0 + m8 * 8);
        }
        #pragma unroll
        for (int i = 0; i < 4; i++) {            // B: 128n x 64k
            int e = i * 256 + t;
            int k8 = e & 7, n = e >> 3;
            cpa16(Bu + (unsigned)(n * 72 + k8 * 8) * 2,
                  g_wqkvb + (size_t)(o0 + n) * CNUM + c0 + k8 * 8);
        }
        asm volatile("cp.async.commit_group;" ::: "memory");
    };

    wmma::fragment<wmma::accumulator, 16, 16, 16, float> acc[2][4];
    #pragma unroll
    for (int i = 0; i < 2; i++)
        #pragma unroll
        for (int j = 0; j < 4; j++) wmma::fill_fragment(acc[i][j], 0.0f);

    loadTile(0);
    for (int kt = 0; kt < 4; kt++) {
        asm volatile("cp.async.wait_group 0;" ::: "memory");
        __syncthreads();
        if (kt < 3) loadTile(kt + 1);
        __nv_bfloat16* As = (__nv_bfloat16*)(qsm + (kt & 1) * QKV_AB);
        __nv_bfloat16* Bs = (__nv_bfloat16*)(qsm + QKV_BOFF + (kt & 1) * QKV_BB);
        #pragma unroll
        for (int kk = 0; kk < 64; kk += 16) {
            wmma::fragment<wmma::matrix_a, 16, 16, 16, __nv_bfloat16, wmma::col_major> a[2];
            wmma::fragment<wmma::matrix_b, 16, 16, 16, __nv_bfloat16, wmma::col_major> bb[4];
            #pragma unroll
            for (int i = 0; i < 2; i++)
                wmma::load_matrix_sync(a[i], As + kk * QKV_AS_ST + (wm * 32 + i * 16), QKV_AS_ST);
            #pragma unroll
            for (int j = 0; j < 4; j++)
                wmma::load_matrix_sync(bb[j], Bs + (wn * 64 + j * 16) * 72 + kk, 72);
            #pragma unroll
            for (int i = 0; i < 2; i++)
                #pragma unroll
                for (int j = 0; j < 4; j++)
                    wmma::mma_sync(acc[i][j], a[i], bb[j], acc[i][j]);
        }
        __syncthreads();         // all warps done with buf (kt&1) before overwrite
    }
    // two-pass epilogue: pass p covers output cols [o0+64p, o0+64p+64)
    #pragma unroll
    for (int p = 0; p < 2; p++) {
        if (wn == p) {
            #pragma unroll
            for (int i = 0; i < 2; i++)
                #pragma unroll
                for (int j = 0; j < 4; j++)
                    wmma::store_matrix_sync(Cs + (wm * 32 + i * 16) * 68 + j * 16,
                                            acc[i][j], 68, wmma::mem_row_major);
        }
        __syncthreads();
        int o0p = o0 + p * 64;
        int which = o0p >> 8;            // 0=q,1=k,2=v
        int head  = (o0p >> 6) & 3;
        __nv_bfloat16* dst = (which == 0) ? g_qb : (which == 1) ? g_kb : g_vb;
        float mul = (which == 0) ? QSCALE : 1.0f;
        #pragma unroll
        for (int i = 0; i < 16; i++) {
            int e = i * 256 + t;          // 4096 bf16x2 pairs
            int n2 = e & 31, m = e >> 5;
            float v0 = (Cs[m * 68 + n2*2]     + bqkv[o0p + n2*2])     * mul;
            float v1 = (Cs[m * 68 + n2*2 + 1] + bqkv[o0p + n2*2 + 1]) * mul;
            *(unsigned*)(dst + (((size_t)((b * NH + head) * HWN + hw0 + m)) << 6) + n2*2) =
                cvtbf2(v0, v1);
        }
        __syncthreads();
    }
}

// ---------------- kernel 4: attention (FA2, Schraudolph bf16 exp2) ---------
// grid (32, 16). 128 threads, 4 warps x 32 q-rows, 2 CTAs/SM. (R8 version)
__global__ __launch_bounds__(128, 2) void attn_kernel() {
    extern __shared__ __align__(16) char dsm[];
    const int SP = 72;
    int t = threadIdx.x;
    int w = t >> 5, l = t & 31;
    int qb = blockIdx.x, bh = blockIdx.y;
    int q0 = qb * 128;
    const __nv_bfloat16* qp = g_qb + (size_t)bh * HWN * HD + (size_t)q0 * HD;
    const __nv_bfloat16* kp = g_kb + (size_t)bh * HWN * HD;
    const __nv_bfloat16* vp = g_vb + (size_t)bh * HWN * HD;

    unsigned su = s2u(dsm);
    unsigned Qs = su;
    unsigned KB0 = su + 128 * SP * 2;
    unsigned KB1 = KB0 + 64 * SP * 2;
    unsigned VB0 = KB1 + 64 * SP * 2;
    unsigned VB1 = VB0 + 64 * SP * 2;

    {
        #pragma unroll
        for (int i = 0; i < 4; i++) {
            int c = i * 128 + t;
            int row = c >> 3, col8 = c & 7;
            unsigned so = (unsigned)(row * SP + col8 * 8) * 2;
            cpa16(KB0 + so, kp + (size_t)row * 64 + col8 * 8);
            cpa16(VB0 + so, vp + (size_t)row * 64 + col8 * 8);
        }
        asm volatile("cp.async.commit_group;" ::: "memory");
    }
    #pragma unroll
    for (int i = 0; i < 8; i++) {
        int c = i * 128 + t;
        int row = c >> 3, col8 = c & 7;
        *(uint4*)(dsm + (size_t)(row * SP + col8 * 8) * 2) =
            *(const uint4*)(qp + (size_t)row * 64 + col8 * 8);
    }
    __syncthreads();

    int lrow_a = l & 15,  lcol_a = (l >> 4) * 8;
    int lrow_k = (l & 7) + ((l >> 4) << 3), lcol_k = ((l >> 3) & 1) * 8;
    int r0 = w * 32;

    unsigned qf[2][4][4];
    #pragma unroll
    for (int mb = 0; mb < 2; mb++)
        #pragma unroll
        for (int kc = 0; kc < 4; kc++)
            ldsm4(qf[mb][kc],
                  Qs + (unsigned)(((r0 + mb*16 + lrow_a) * SP + kc*16 + lcol_a) * 2));

    float oacc[2][8][4];
    #pragma unroll
    for (int mb = 0; mb < 2; mb++)
        #pragma unroll
        for (int j = 0; j < 8; j++)
            #pragma unroll
            for (int i = 0; i < 4; i++) oacc[mb][j][i] = 0.f;
    float rs[4] = {0.f, 0.f, 0.f, 0.f};

    for (int kb = 0; kb < 64; kb++) {
        asm volatile("cp.async.wait_group 0;" ::: "memory");
        __syncthreads();
        if (kb + 1 < 64) {
            int k0 = (kb + 1) * 64;
            unsigned kd = ((kb + 1) & 1) ? KB1 : KB0;
            unsigned vd = ((kb + 1) & 1) ? VB1 : VB0;
            #pragma unroll
            for (int i = 0; i < 4; i++) {
                int c = i * 128 + t;
                int row = c >> 3, col8 = c & 7;
                unsigned so = (unsigned)(row * SP + col8 * 8) * 2;
                cpa16(kd + so, kp + (size_t)(k0 + row) * 64 + col8 * 8);
                cpa16(vd + so, vp + (size_t)(k0 + row) * 64 + col8 * 8);
            }
            asm volatile("cp.async.commit_group;" ::: "memory");
        }
        unsigned kS = (kb & 1) ? KB1 : KB0;
        unsigned vS = (kb & 1) ? VB1 : VB0;

        unsigned pf[2][4][4];
        #pragma unroll
        for (int ph = 0; ph < 2; ph++) {
            float s[2][2][2][4];
            #pragma unroll
            for (int g2 = 0; g2 < 2; g2++)
                #pragma unroll
                for (int mb = 0; mb < 2; mb++)
                    #pragma unroll
                    for (int h = 0; h < 2; h++)
                        #pragma unroll
                        for (int i = 0; i < 4; i++) s[g2][mb][h][i] = 0.f;
            #pragma unroll
            for (int kc = 0; kc < 4; kc++) {
                #pragma unroll
                for (int g2 = 0; g2 < 2; g2++) {
                    int g = ph * 2 + g2;
                    unsigned bb[4];
                    ldsm4(bb, kS + (unsigned)(((g*16 + lrow_k) * SP + kc*16 + lcol_k) * 2));
                    mma_bf(s[g2][0][0], qf[0][kc], bb[0], bb[1]);
                    mma_bf(s[g2][0][1], qf[0][kc], bb[2], bb[3]);
                    mma_bf(s[g2][1][0], qf[1][kc], bb[0], bb[1]);
                    mma_bf(s[g2][1][1], qf[1][kc], bb[2], bb[3]);
                }
            }
            #pragma unroll
            for (int g2 = 0; g2 < 2; g2++) {
                int g = ph * 2 + g2;
                #pragma unroll
                for (int mb = 0; mb < 2; mb++) {
                    float e0 = ex2t(s[g2][mb][0][0]), e1 = ex2t(s[g2][mb][0][1]);
                    float e2 = ex2t(s[g2][mb][0][2]), e3 = ex2t(s[g2][mb][0][3]);
                    float f0 = ex2t(s[g2][mb][1][0]), f1 = ex2t(s[g2][mb][1][1]);
                    float f2 = ex2t(s[g2][mb][1][2]), f3 = ex2t(s[g2][mb][1][3]);
                    pf[mb][g][0] = bfpack(e0, e1);
                    pf[mb][g][1] = bfpack(e2, e3);
                    pf[mb][g][2] = bfpack(f0, f1);
                    pf[mb][g][3] = bfpack(f2, f3);
                    rs[mb*2+0] += (bfval(e0) + bfval(e1)) + (bfval(f0) + bfval(f1));
                    rs[mb*2+1] += (bfval(e2) + bfval(e3)) + (bfval(f2) + bfval(f3));
                }
            }
        }
        #pragma unroll
        for (int g = 0; g < 4; g++) {
            #pragma unroll
            for (int dg = 0; dg < 4; dg++) {
                unsigned vv[4];
                ldsm4t(vv, vS + (unsigned)(((g*16 + lrow_a) * SP + dg*16 + lcol_a) * 2));
                mma_bf(oacc[0][2*dg],   pf[0][g], vv[0], vv[1]);
                mma_bf(oacc[0][2*dg+1], pf[0][g], vv[2], vv[3]);
                mma_bf(oacc[1][2*dg],   pf[1][g], vv[0], vv[1]);
                mma_bf(oacc[1][2*dg+1], pf[1][g], vv[2], vv[3]);
            }
        }
    }

    #pragma unroll
    for (int i = 0; i < 4; i++) {
        rs[i] += __shfl_xor_sync(0xffffffffu, rs[i], 1);
        rs[i] += __shfl_xor_sync(0xffffffffu, rs[i], 2);
    }
    int b = bh >> 2, h = bh & 3;
    __nv_bfloat16* aop = g_ao + ((size_t)b * HWN + q0) * CNUM + h * HD;
    #pragma unroll
    for (int mb = 0; mb < 2; mb++) {
        float i0 = 1.0f / rs[mb*2], i1 = 1.0f / rs[mb*2+1];
        int row0 = r0 + mb*16 + (l >> 2);
        int cbase = (l & 3) * 2;
        #pragma unroll
        for (int j = 0; j < 8; j++) {
            *(unsigned*)(aop + (size_t)row0 * CNUM + j*8 + cbase) =
                cvtbf2(oacc[mb][j][0] * i0, oacc[mb][j][1] * i0);
            *(unsigned*)(aop + (size_t)(row0 + 8) * CNUM + j*8 + cbase) =
                cvtbf2(oacc[mb][j][2] * i1, oacc[mb][j][3] * i1);
        }
    }
}

// ---------------- kernel 5: proj GEMM + residual (dbl-buffered, aliased C) -
// smem: A0 A1 (128x72 bf16, 18432 each) | B0 B1 (18432 each); C aliases base
#define PROJ_AB   18432
#define PROJ_BOFF (2*PROJ_AB)
#define PROJ_SMEM (4*PROJ_AB)   // 73728

__global__ __launch_bounds__(256) void proj_kernel(const float* __restrict__ x,
                                                   const float* __restrict__ bproj,
                                                   float* __restrict__ out) {
    extern __shared__ char psm[];
    float* Cs = (float*)psm;                                  // aliases A0+A1
    int nt = blockIdx.x;     // 0..1
    int mt = blockIdx.y;     // 0..127
    int p0 = mt * 128;
    int b  = p0 >> 12;
    int hw0 = p0 & (HWN - 1);
    int o0 = nt * 128;
    int t = threadIdx.x, w = t >> 5, wm = w & 3, wn = w >> 2;
    unsigned su = s2u(psm);

    auto loadTile = [&](int kt) {
        int c0 = kt * 64;
        unsigned Au = su + (unsigned)(kt & 1) * PROJ_AB;
        unsigned Bu = su + PROJ_BOFF + (unsigned)(kt & 1) * PROJ_AB;
        #pragma unroll
        for (int i = 0; i < 4; i++) {            // A: 128m x 64k
            int e = i * 256 + t;
            int k8 = e & 7, m = e >> 3;
            cpa16(Au + (unsigned)(m * 72 + k8 * 8) * 2,
                  g_ao + ((size_t)(p0 + m)) * CNUM + c0 + k8 * 8);
        }
        #pragma unroll
        for (int i = 0; i < 4; i++) {            // B: 128n x 64k
            int e = i * 256 + t;
            int k8 = e & 7, n = e >> 3;
            cpa16(Bu + (unsigned)(n * 72 + k8 * 8) * 2,
                  g_wprojb + (size_t)(o0 + n) * CNUM + c0 + k8 * 8);
        }
        asm volatile("cp.async.commit_group;" ::: "memory");
    };

    wmma::fragment<wmma::accumulator, 16, 16, 16, float> acc[2][4];
    #pragma unroll
    for (int i = 0; i < 2; i++)
        #pragma unroll
        for (int j = 0; j < 4; j++) wmma::fill_fragment(acc[i][j], 0.0f);

    loadTile(0);
    for (int kt = 0; kt < 4; kt++) {
        asm volatile("cp.async.wait_group 0;" ::: "memory");
        __syncthreads();
        if (kt < 3) loadTile(kt + 1);
        __nv_bfloat16* As = (__nv_bfloat16*)(psm + (kt & 1) * PROJ_AB);
        __nv_bfloat16* Bs = (__nv_bfloat16*)(psm + PROJ_BOFF + (kt & 1) * PROJ_AB);
        #pragma unroll
        for (int kk = 0; kk < 64; kk += 16) {
            wmma::fragment<wmma::matrix_a, 16, 16, 16, __nv_bfloat16, wmma::row_major> a[2];
            wmma::fragment<wmma::matrix_b, 16, 16, 16, __nv_bfloat16, wmma::col_major> bb[4];
            #pragma unroll
            for (int i = 0; i < 2; i++)
                wmma::load_matrix_sync(a[i], As + (wm * 32 + i * 16) * 72 + kk, 72);
            #pragma unroll
            for (int j = 0; j < 4; j++)
                wmma::load_matrix_sync(bb[j], Bs + (wn * 64 + j * 16) * 72 + kk, 72);
            #pragma unroll
            for (int i = 0; i < 2; i++)
                #pragma unroll
                for (int j = 0; j < 4; j++)
                    wmma::mma_sync(acc[i][j], a[i], bb[j], acc[i][j]);
        }
        __syncthreads();
    }
    // two-pass epilogue
    #pragma unroll
    for (int p = 0; p < 2; p++) {
        if (wn == p) {
            #pragma unroll
            for (int i = 0; i < 2; i++)
                #pragma unroll
                for (int j = 0; j < 4; j++)
                    wmma::store_matrix_sync(Cs + (wm * 32 + i * 16) * 68 + j * 16,
                                            acc[i][j], 68, wmma::mem_row_major);
        }
        __syncthreads();
        int o0p = o0 + p * 64;
        #pragma unroll
        for (int i = 0; i < 32; i++) {
            int e = i * 256 + t;
            int m = e & 127, n = e >> 7;
            size_t oidx = (((size_t)(b * CNUM + o0p + n)) << 12) + hw0 + m;
            out[oidx] = x[oidx] + Cs[m * 68 + n] + bproj[o0p + n];
        }
        __syncthreads();
    }
}

// ---------------- launch ----------------------------------------------------
extern "C" void kernel_launch(void* const* d_in, const int* in_sizes, int n_in,
                              void* d_out, int out_size) {
    const float* x      = (const float*)d_in[0];
    const float* gamma  = (const float*)d_in[1];
    const float* beta   = (const float*)d_in[2];
    const float* w_qkv  = (const float*)d_in[3];
    const float* b_qkv  = (const float*)d_in[4];
    const float* w_proj = (const float*)d_in[5];
    const float* b_proj = (const float*)d_in[6];
    float* out = (float*)d_out;

    gn_partial<<<320, 256>>>(x, w_qkv, w_proj);
    gn_apply<<<1024, 256>>>(x, gamma, beta);

    cudaFuncSetAttribute(qkv_kernel, cudaFuncAttributeMaxDynamicSharedMemorySize, QKV_SMEM);
    qkv_kernel<<<dim3(6, 128), 256, QKV_SMEM>>>(b_qkv);

    const int attn_smem = (128 + 4 * 64) * 72 * 2;   // 55296 B
    cudaFuncSetAttribute(attn_kernel, cudaFuncAttributeMaxDynamicSharedMemorySize, attn_smem);
    attn_kernel<<<dim3(32, 16), 128, attn_smem>>>();

    cudaFuncSetAttribute(proj_kernel, cudaFuncAttributeMaxDynamicSharedMemorySize, PROJ_SMEM);
    proj_kernel<<<dim3(2, 128), 256, PROJ_SMEM>>>(x, b_proj, out);
}